// round 7
// baseline (speedup 1.0000x reference)
#include <cuda_runtime.h>
#include <cstdint>

// Problem constants
#define B_     8
#define CDIM   64
#define NPOS   9216      // 96*96
#define INNER  128
#define O3     384       // 3*INNER
#define HEADS  4
#define DHEAD  32
#define NCH    9
#define CHUNK  1024
#define NGC    (32 * NCH)   // 288 (g, ch) pairs
#define GN_TILES 72

// Scratch (device globals — no allocations allowed)
__device__ __align__(16) float g_qkv[(size_t)B_ * O3 * NPOS];      // [b][o][n]
__device__ float g_part[B_][8][GN_TILES][2];                        // groupnorm partials
__device__ __align__(16) float g_Apart[NGC][8][DHEAD * DHEAD];      // partial A (unnormalized)
__device__ __align__(16) float g_Weff[B_ * NCH][2][CDIM][INNER];    // fused weights hi/lo

// ---------------------------------------------------------------------------
__device__ __forceinline__ uint32_t f2tf(float x) {
    uint32_t r;
    asm("cvt.rna.tf32.f32 %0, %1;" : "=r"(r) : "f"(x));
    return r;
}

#define MMA(d, a, b)                                                          \
    asm volatile(                                                             \
        "mma.sync.aligned.m16n8k8.row.col.f32.tf32.tf32.f32 "                 \
        "{%0,%1,%2,%3},{%4,%5,%6,%7},{%8,%9},{%0,%1,%2,%3};"                  \
        : "+f"((d)[0]), "+f"((d)[1]), "+f"((d)[2]), "+f"((d)[3])              \
        : "r"((a)[0]), "r"((a)[1]), "r"((a)[2]), "r"((a)[3]),                 \
          "r"((b)[0]), "r"((b)[1]))

// Packed A staging: element (row, c) of an [M x K] tile maps to one float in
// packed[((k8*nM + m16)*8 + g)*4 + tig] (float4 units), component hi8 + 2*hi4,
// so that a warp's mma A-fragment is exactly one LDS.128 per thread.

// ---------------------------------------------------------------------------
// K1 (mma): qkv[b][o][n] = sum_c W_qkv[o][c] * x[b][c][n]
// A (W tile) packed hi/lo in smem; B (x) streamed + prefetched from global.
// CTA tile [128 M x 128 N], K=64. grid (72, 3, 8), 256 threads, occ 2.
// ---------------------------------------------------------------------------
#define K1_SMEM (8192 * 2 * 4)   // 64 KB

__global__ __launch_bounds__(256, 2) void qkv_mma_kernel(const float* __restrict__ x,
                                                         const float* __restrict__ Wq) {
    extern __shared__ uint32_t smu[];
    uint32_t* Ahi = smu;          // 8192 words, packed
    uint32_t* Alo = Ahi + 8192;

    const int b = blockIdx.z, mt = blockIdx.y, n0 = blockIdx.x * 128;
    const int tid = threadIdx.x;

    // stage + split W tile [128 M x 64 K] into packed fragment layout
    for (int idx = tid; idx < 128 * 16; idx += 256) {
        int row = idx >> 4, c4 = (idx & 15) * 4;
        float4 w = *(const float4*)(Wq + (size_t)(mt * 128 + row) * CDIM + c4);
        float v[4] = {w.x, w.y, w.z, w.w};
        int m16 = row >> 4, gg = row & 15;
        int gp = gg & 7, hi8 = gg >> 3;
#pragma unroll
        for (int j = 0; j < 4; j++) {
            int cc = c4 + j;
            int k8 = cc >> 3, ct = cc & 7;
            int tg = ct & 3, hi4 = ct >> 2;
            int widx = ((((k8 << 3) + m16) << 3) + gp) * 4 + tg;
            int comp = hi8 + 2 * hi4;
            uint32_t h = f2tf(v[j]);
            Ahi[widx * 4 + comp] = h;
            Alo[widx * 4 + comp] = f2tf(v[j] - __uint_as_float(h));
        }
    }
    __syncthreads();

    const int wid = tid >> 5, lane = tid & 31, g = lane >> 2, tig = lane & 3;
    const int wm16 = (wid >> 2) * 4, wn = (wid & 3) * 32;
    const float* xb = x + (size_t)b * CDIM * NPOS + n0;

    float c[4][4][4];
#pragma unroll
    for (int i = 0; i < 4; i++)
#pragma unroll
        for (int j = 0; j < 4; j++)
#pragma unroll
            for (int q = 0; q < 4; q++) c[i][j][q] = 0.f;

    // prefetch k8 = 0 B values
    float rb0[4], rb1[4];
#pragma unroll
    for (int nf = 0; nf < 4; nf++) {
        const float* xr = xb + (size_t)tig * NPOS + wn + nf * 8 + g;
        rb0[nf] = __ldg(xr);
        rb1[nf] = __ldg(xr + 4 * NPOS);
    }

#pragma unroll
    for (int k8 = 0; k8 < 8; k8++) {
        float nb0[4], nb1[4];
        if (k8 < 7) {
#pragma unroll
            for (int nf = 0; nf < 4; nf++) {
                const float* xr = xb + (size_t)((k8 + 1) * 8 + tig) * NPOS + wn + nf * 8 + g;
                nb0[nf] = __ldg(xr);
                nb1[nf] = __ldg(xr + 4 * NPOS);
            }
        }
        uint32_t bh[4][2], bl[4][2];
#pragma unroll
        for (int nf = 0; nf < 4; nf++) {
            uint32_t h0 = f2tf(rb0[nf]), h1 = f2tf(rb1[nf]);
            bh[nf][0] = h0; bh[nf][1] = h1;
            bl[nf][0] = f2tf(rb0[nf] - __uint_as_float(h0));
            bl[nf][1] = f2tf(rb1[nf] - __uint_as_float(h1));
        }
#pragma unroll
        for (int mf = 0; mf < 4; mf++) {
            int pidx = ((((k8 << 3) + wm16 + mf) << 3) + g) * 4 + tig;
            uint4 avh = ((const uint4*)Ahi)[pidx];
            uint4 avl = ((const uint4*)Alo)[pidx];
            uint32_t ah[4] = {avh.x, avh.y, avh.z, avh.w};
            uint32_t al[4] = {avl.x, avl.y, avl.z, avl.w};
#pragma unroll
            for (int nf = 0; nf < 4; nf++) {
                MMA(c[mf][nf], ah, bh[nf]);
                MMA(c[mf][nf], ah, bl[nf]);
                MMA(c[mf][nf], al, bh[nf]);
            }
        }
#pragma unroll
        for (int nf = 0; nf < 4; nf++) { rb0[nf] = nb0[nf]; rb1[nf] = nb1[nf]; }
    }

    float* op = g_qkv + ((size_t)b * O3 + mt * 128 + wm16 * 16) * NPOS + n0 + wn;
#pragma unroll
    for (int mf = 0; mf < 4; mf++)
#pragma unroll
        for (int nf = 0; nf < 4; nf++) {
            int col = nf * 8 + tig * 2;
            *(float2*)(op + (size_t)(mf * 16 + g) * NPOS + col) =
                make_float2(c[mf][nf][0], c[mf][nf][1]);
            *(float2*)(op + (size_t)(mf * 16 + g + 8) * NPOS + col) =
                make_float2(c[mf][nf][2], c[mf][nf][3]);
        }
}

// ---------------------------------------------------------------------------
// ATT2: partial (unnormalized) A over 128 positions. grid (9, 32, 8), 128 thr.
// (unchanged)
// ---------------------------------------------------------------------------
#define A2_PAD 132
#define A2_ARR (DHEAD * A2_PAD)
#define A2_SMEM (4 * A2_ARR * 4)

__global__ __launch_bounds__(128, 3) void att_a_kernel() {
    extern __shared__ uint32_t sm2[];
    uint32_t* Eqh = sm2;
    uint32_t* Eql = Eqh + A2_ARR;
    uint32_t* Ksh = Eql + A2_ARR;
    uint32_t* Ksl = Ksh + A2_ARR;
    float* Apart = (float*)sm2;   // alias after mma: [4][32][33]

    const int ch = blockIdx.x, g = blockIdx.y, sub = blockIdx.z;
    const int gc = g * NCH + ch;
    const int b = g >> 2, head = g & 3;
    const int tid = threadIdx.x, lane = tid & 31, wrp = tid >> 5;
    const int j = tid;

    const float* qbase = g_qkv + ((size_t)(b * O3 + head * DHEAD)) * NPOS + ch * CHUNK + sub * 128;
    const float* kbase = qbase + (size_t)INNER * NPOS;

    float kr[DHEAD];
#pragma unroll
    for (int d = 0; d < DHEAD; d++) kr[d] = kbase[(size_t)d * NPOS + j];
    float km = -1e30f;
#pragma unroll
    for (int d = 0; d < DHEAD; d++) km = fmaxf(km, kr[d]);
    float ks = 0.f;
#pragma unroll
    for (int d = 0; d < DHEAD; d++) { kr[d] = __expf(kr[d] - km); ks += kr[d]; }
    float kinv = 1.0f / ks;
#pragma unroll
    for (int d = 0; d < DHEAD; d++) {
        float v = kr[d] * kinv;
        uint32_t h = f2tf(v);
        Ksh[d * A2_PAD + j] = h;
        Ksl[d * A2_PAD + j] = f2tf(v - __uint_as_float(h));
    }

    float qr[DHEAD];
#pragma unroll
    for (int d = 0; d < DHEAD; d++) qr[d] = qbase[(size_t)d * NPOS + j];
#pragma unroll
    for (int d = 0; d < DHEAD; d++) {
        float v = __expf(qr[d]);
        uint32_t h = f2tf(v);
        Eqh[d * A2_PAD + j] = h;
        Eql[d * A2_PAD + j] = f2tf(v - __uint_as_float(h));
    }
    __syncthreads();

    const int gq = lane >> 2, tig = lane & 3;
    float acc[2][4][4];
#pragma unroll
    for (int i = 0; i < 2; i++)
#pragma unroll
        for (int jj = 0; jj < 4; jj++)
#pragma unroll
            for (int q = 0; q < 4; q++) acc[i][jj][q] = 0.f;

#pragma unroll
    for (int kk = 0; kk < 4; kk++) {
        const int kb = (wrp * 4 + kk) * 8;
        uint32_t ah[2][4], al[2][4];
#pragma unroll
        for (int mf = 0; mf < 2; mf++) {
            int r0 = (mf * 16 + gq) * A2_PAD + kb + tig;
            int r1 = r0 + 8 * A2_PAD;
            ah[mf][0] = Eqh[r0]; ah[mf][1] = Eqh[r1];
            ah[mf][2] = Eqh[r0 + 4]; ah[mf][3] = Eqh[r1 + 4];
            al[mf][0] = Eql[r0]; al[mf][1] = Eql[r1];
            al[mf][2] = Eql[r0 + 4]; al[mf][3] = Eql[r1 + 4];
        }
        uint32_t bh[4][2], bl[4][2];
#pragma unroll
        for (int nf = 0; nf < 4; nf++) {
            int c0 = (nf * 8 + gq) * A2_PAD + kb + tig;
            bh[nf][0] = Ksh[c0]; bh[nf][1] = Ksh[c0 + 4];
            bl[nf][0] = Ksl[c0]; bl[nf][1] = Ksl[c0 + 4];
        }
#pragma unroll
        for (int mf = 0; mf < 2; mf++)
#pragma unroll
            for (int nf = 0; nf < 4; nf++) {
                MMA(acc[mf][nf], ah[mf], bh[nf]);
                MMA(acc[mf][nf], ah[mf], bl[nf]);
                MMA(acc[mf][nf], al[mf], bh[nf]);
            }
    }
    __syncthreads();

#pragma unroll
    for (int mf = 0; mf < 2; mf++)
#pragma unroll
        for (int nf = 0; nf < 4; nf++) {
            int row = mf * 16 + gq, col = nf * 8 + tig * 2;
            Apart[(wrp * 32 + row) * 33 + col]     = acc[mf][nf][0];
            Apart[(wrp * 32 + row) * 33 + col + 1] = acc[mf][nf][1];
            Apart[(wrp * 32 + row + 8) * 33 + col]     = acc[mf][nf][2];
            Apart[(wrp * 32 + row + 8) * 33 + col + 1] = acc[mf][nf][3];
        }
    __syncthreads();

    float* out = g_Apart[gc][sub];
#pragma unroll
    for (int r = 0; r < 8; r++) {
        int idx = tid + 128 * r;
        int d = idx >> 5, dp = idx & 31;
        float s = 0.f;
#pragma unroll
        for (int w = 0; w < 4; w++) s += Apart[(w * 32 + d) * 33 + dp];
        out[idx] = s;
    }
}

// ---------------------------------------------------------------------------
// WEFF: grid (9, 8, 4), 256 threads (unchanged)
// ---------------------------------------------------------------------------
__global__ __launch_bounds__(256, 6) void weff_kernel(const float* __restrict__ Wout) {
    __shared__ float A_s[DHEAD][DHEAD + 1];
    __shared__ float W_s[CDIM][DHEAD + 1];
    __shared__ float rinv[DHEAD];
    const int ch = blockIdx.x, b = blockIdx.y, head = blockIdx.z;
    const int cc = b * NCH + ch;
    const int gc = (b * HEADS + head) * NCH + ch;
    const int tid = threadIdx.x;

#pragma unroll
    for (int r = 0; r < 4; r++) {
        int idx = tid + 256 * r;
        const float* ap = g_Apart[gc][0] + idx;
        float s = 0.f;
#pragma unroll
        for (int sub = 0; sub < 8; sub++) s += ap[sub * DHEAD * DHEAD];
        A_s[idx >> 5][idx & 31] = s;
    }
#pragma unroll
    for (int r = 0; r < 8; r++) {
        int idx = tid + 256 * r;
        int o = idx >> 5, d = idx & 31;
        W_s[o][d] = Wout[(size_t)o * INNER + head * DHEAD + d];
    }
    __syncthreads();

    if (tid < DHEAD) {
        float s = 0.f;
#pragma unroll
        for (int dp = 0; dp < DHEAD; dp++) s += A_s[tid][dp];
        rinv[tid] = 1.0f / s;
    }
    __syncthreads();
#pragma unroll
    for (int r = 0; r < 4; r++) {
        int idx = tid + 256 * r;
        A_s[idx >> 5][idx & 31] *= rinv[idx >> 5];
    }
    __syncthreads();

#pragma unroll
    for (int r = 0; r < 8; r++) {
        int idx = tid + 256 * r;
        int o = idx >> 5, dp = idx & 31;
        float acc = 0.f;
#pragma unroll
        for (int d = 0; d < DHEAD; d++) acc += W_s[o][d] * A_s[d][dp];
        uint32_t h = f2tf(acc);
        g_Weff[cc][0][o][head * DHEAD + dp] = __uint_as_float(h);
        g_Weff[cc][1][o][head * DHEAD + dp] = __uint_as_float(f2tf(acc - __uint_as_float(h)));
    }
}

// ---------------------------------------------------------------------------
// K3' (fused): y = W_eff(b,ch) @ V + b_out, groupnorm partials.
// A (W_eff) packed hi/lo in smem; B (V) streamed + prefetched from global.
// CTA tile [64 M x 128 N], K=128. grid (72, 8), 256 threads, occ 2.
// ---------------------------------------------------------------------------
#define K3_SMEM (8192 * 2 * 4)   // 64 KB

__global__ __launch_bounds__(256, 2) void outproj_mma_kernel(const float* __restrict__ bout,
                                                             float* __restrict__ y) {
    extern __shared__ uint32_t smu[];
    uint32_t* Ahi = smu;          // 8192 words packed
    uint32_t* Alo = Ahi + 8192;
    __shared__ float swp[8][8][2];

    const int b = blockIdx.y, n0 = blockIdx.x * 128, tid = threadIdx.x;
    const int cc = b * NCH + (n0 / CHUNK);

    // stage pre-split W_eff [64 M x 128 K] into packed fragment layout
    for (int idx = tid; idx < 64 * 32; idx += 256) {
        int row = idx >> 5, c4 = (idx & 31) * 4;
        float4 h4 = *(const float4*)(&g_Weff[cc][0][row][c4]);
        float4 l4 = *(const float4*)(&g_Weff[cc][1][row][c4]);
        float hv[4] = {h4.x, h4.y, h4.z, h4.w};
        float lv[4] = {l4.x, l4.y, l4.z, l4.w};
        int m16 = row >> 4, gg = row & 15;
        int gp = gg & 7, hi8 = gg >> 3;
#pragma unroll
        for (int j = 0; j < 4; j++) {
            int ccol = c4 + j;
            int k8 = ccol >> 3, ct = ccol & 7;
            int tg = ct & 3, hi4 = ct >> 2;
            int widx = ((((k8 << 2) + m16) << 3) + gp) * 4 + tg;
            int comp = hi8 + 2 * hi4;
            Ahi[widx * 4 + comp] = __float_as_uint(hv[j]);
            Alo[widx * 4 + comp] = __float_as_uint(lv[j]);
        }
    }
    __syncthreads();

    const int wid = tid >> 5, lane = tid & 31, g = lane >> 2, tig = lane & 3;
    const int wn = wid * 16;
    const float* vbase = g_qkv + ((size_t)b * O3 + 2 * INNER) * NPOS + n0;

    float acc[4][2][4];
#pragma unroll
    for (int i = 0; i < 4; i++)
#pragma unroll
        for (int j = 0; j < 2; j++)
#pragma unroll
            for (int q = 0; q < 4; q++) acc[i][j][q] = 0.f;

    float rb0[2], rb1[2];
#pragma unroll
    for (int nf = 0; nf < 2; nf++) {
        const float* vr = vbase + (size_t)tig * NPOS + wn + nf * 8 + g;
        rb0[nf] = __ldg(vr);
        rb1[nf] = __ldg(vr + 4 * NPOS);
    }

#pragma unroll
    for (int k8 = 0; k8 < 16; k8++) {
        float nb0[2], nb1[2];
        if (k8 < 15) {
#pragma unroll
            for (int nf = 0; nf < 2; nf++) {
                const float* vr = vbase + (size_t)((k8 + 1) * 8 + tig) * NPOS + wn + nf * 8 + g;
                nb0[nf] = __ldg(vr);
                nb1[nf] = __ldg(vr + 4 * NPOS);
            }
        }
        uint32_t bh[2][2], bl[2][2];
#pragma unroll
        for (int nf = 0; nf < 2; nf++) {
            uint32_t h0 = f2tf(rb0[nf]), h1 = f2tf(rb1[nf]);
            bh[nf][0] = h0; bh[nf][1] = h1;
            bl[nf][0] = f2tf(rb0[nf] - __uint_as_float(h0));
            bl[nf][1] = f2tf(rb1[nf] - __uint_as_float(h1));
        }
#pragma unroll
        for (int mf = 0; mf < 4; mf++) {
            int pidx = ((((k8 << 2) + mf) << 3) + g) * 4 + tig;
            uint4 avh = ((const uint4*)Ahi)[pidx];
            uint4 avl = ((const uint4*)Alo)[pidx];
            uint32_t ah[4] = {avh.x, avh.y, avh.z, avh.w};
            uint32_t al[4] = {avl.x, avl.y, avl.z, avl.w};
#pragma unroll
            for (int nf = 0; nf < 2; nf++) {
                MMA(acc[mf][nf], ah, bh[nf]);
                MMA(acc[mf][nf], ah, bl[nf]);
                MMA(acc[mf][nf], al, bh[nf]);
            }
        }
#pragma unroll
        for (int nf = 0; nf < 2; nf++) { rb0[nf] = nb0[nf]; rb1[nf] = nb1[nf]; }
    }

    float gs[8], gq[8];
#pragma unroll
    for (int i = 0; i < 8; i++) { gs[i] = 0.f; gq[i] = 0.f; }

    float* yp = y + (size_t)b * CDIM * NPOS + n0 + wn;
#pragma unroll
    for (int mf = 0; mf < 4; mf++) {
        float bias0 = __ldg(bout + mf * 16 + g);
        float bias1 = __ldg(bout + mf * 16 + g + 8);
#pragma unroll
        for (int nf = 0; nf < 2; nf++) {
            int col = nf * 8 + tig * 2;
            float v0 = acc[mf][nf][0] + bias0, v1 = acc[mf][nf][1] + bias0;
            float v2 = acc[mf][nf][2] + bias1, v3 = acc[mf][nf][3] + bias1;
            *(float2*)(yp + (size_t)(mf * 16 + g) * NPOS + col) = make_float2(v0, v1);
            *(float2*)(yp + (size_t)(mf * 16 + g + 8) * NPOS + col) = make_float2(v2, v3);
            gs[2 * mf]     += v0 + v1;
            gq[2 * mf]     += v0 * v0 + v1 * v1;
            gs[2 * mf + 1] += v2 + v3;
            gq[2 * mf + 1] += v2 * v2 + v3 * v3;
        }
    }

#pragma unroll
    for (int gr = 0; gr < 8; gr++) {
        float s = gs[gr], q = gq[gr];
        for (int off = 16; off; off >>= 1) {
            s += __shfl_xor_sync(0xffffffffu, s, off);
            q += __shfl_xor_sync(0xffffffffu, q, off);
        }
        if (lane == 0) { swp[wid][gr][0] = s; swp[wid][gr][1] = q; }
    }
    __syncthreads();
    if (tid < 16) {
        int gr = tid >> 1, qq = tid & 1;
        float s = 0.f;
#pragma unroll
        for (int w = 0; w < 8; w++) s += swp[w][gr][qq];
        g_part[b][gr][blockIdx.x][qq] = s;
    }
}

// ---------------------------------------------------------------------------
// K4: groupnorm finalize, float4-vectorized. grid (9, 8), 256 threads.
// ---------------------------------------------------------------------------
__global__ __launch_bounds__(256, 4) void gnorm_kernel(float* __restrict__ y,
                                                       const float* __restrict__ gamma,
                                                       const float* __restrict__ beta) {
    __shared__ float tmp[8][2];
    __shared__ float mu[8], rs[8];
    const int b = blockIdx.y, n0 = blockIdx.x * 1024, tid = threadIdx.x;

    if (tid < 16) {
        int g = tid >> 1, qq = tid & 1;
        float s = 0.f;
        for (int t = 0; t < GN_TILES; t++) s += g_part[b][g][t][qq];
        tmp[g][qq] = s;
    }
    __syncthreads();
    if (tid < 8) {
        const float invn = 1.0f / (8.0f * NPOS);
        float m = tmp[tid][0] * invn;
        float v = tmp[tid][1] * invn - m * m;
        mu[tid] = m;
        rs[tid] = rsqrtf(v + 1e-5f);
    }
    __syncthreads();

    float* yb = y + (size_t)b * CDIM * NPOS + n0 + tid * 4;
#pragma unroll 4
    for (int c = 0; c < CDIM; c++) {
        float4* p = (float4*)(yb + (size_t)c * NPOS);
        float4 v = *p;
        int g = c >> 3;
        float sc = rs[g] * __ldg(gamma + c);
        float sh = __ldg(beta + c) - mu[g] * sc;
        v.x = v.x * sc + sh;
        v.y = v.y * sc + sh;
        v.z = v.z * sc + sh;
        v.w = v.w * sc + sh;
        *p = v;
    }
}

// ---------------------------------------------------------------------------
extern "C" void kernel_launch(void* const* d_in, const int* in_sizes, int n_in,
                              void* d_out, int out_size) {
    const float* x     = (const float*)d_in[0];
    const float* Wqkv  = (const float*)d_in[1];
    const float* Wout  = (const float*)d_in[2];
    const float* bout  = (const float*)d_in[3];
    const float* gamma = (const float*)d_in[4];
    const float* beta  = (const float*)d_in[5];
    float* y = (float*)d_out;

    cudaFuncSetAttribute(qkv_mma_kernel, cudaFuncAttributeMaxDynamicSharedMemorySize, K1_SMEM);
    cudaFuncSetAttribute(att_a_kernel, cudaFuncAttributeMaxDynamicSharedMemorySize, A2_SMEM);
    cudaFuncSetAttribute(outproj_mma_kernel, cudaFuncAttributeMaxDynamicSharedMemorySize, K3_SMEM);

    qkv_mma_kernel<<<dim3(72, 3, B_), 256, K1_SMEM>>>(x, Wqkv);
    att_a_kernel<<<dim3(NCH, 32, 8), 128, A2_SMEM>>>();
    weff_kernel<<<dim3(NCH, B_, HEADS), 256>>>(Wout);
    outproj_mma_kernel<<<dim3(GN_TILES, B_), 256, K3_SMEM>>>(bout, y);
    gnorm_kernel<<<dim3(NCH, B_), 256>>>(y, gamma, beta);
}

// round 8
// speedup vs baseline: 1.3001x; 1.3001x over previous
#include <cuda_runtime.h>
#include <cstdint>

// Problem constants
#define B_     8
#define CDIM   64
#define NPOS   9216      // 96*96
#define INNER  128
#define O3     384       // 3*INNER
#define HEADS  4
#define DHEAD  32
#define NCH    9
#define CHUNK  1024
#define NGC    (32 * NCH)   // 288 (g, ch) pairs
#define GN_TILES 72

// Scratch (device globals — no allocations allowed)
__device__ __align__(16) float g_qkv[(size_t)B_ * O3 * NPOS];      // [b][o][n] (q,k used)
__device__ float g_part[B_][8][GN_TILES][2];                        // groupnorm partials
__device__ __align__(16) float g_Apart[NGC][8][DHEAD * DHEAD];      // partial A (unnormalized)
__device__ __align__(16) float g_W2part[B_ * NCH][HEADS][CDIM * CDIM]; // per-head W2 partials
__device__ __align__(16) float g_W2[B_ * NCH][2][CDIM][CDIM];       // fused weights hi/lo

// ---------------------------------------------------------------------------
__device__ __forceinline__ uint32_t f2tf(float x) {
    uint32_t r;
    asm("cvt.rna.tf32.f32 %0, %1;" : "=r"(r) : "f"(x));
    return r;
}

#define MMA(d, a, b)                                                          \
    asm volatile(                                                             \
        "mma.sync.aligned.m16n8k8.row.col.f32.tf32.tf32.f32 "                 \
        "{%0,%1,%2,%3},{%4,%5,%6,%7},{%8,%9},{%0,%1,%2,%3};"                  \
        : "+f"((d)[0]), "+f"((d)[1]), "+f"((d)[2]), "+f"((d)[3])              \
        : "r"((a)[0]), "r"((a)[1]), "r"((a)[2]), "r"((a)[3]),                 \
          "r"((b)[0]), "r"((b)[1]))

// ---------------------------------------------------------------------------
// K1 (mma): qk[b][o][n] = sum_c W_qkv[o][c] * x[b][c][n], o in [0, 256) only.
// A (W tile, hi/lo) in padded smem; B (x) streamed from global (R6 form).
// CTA tile [128 M x 128 N], K=64. grid (72, 2, 8), 256 threads, occ 2.
// ---------------------------------------------------------------------------
#define K1_APAD 68
#define K1_SMEM (128 * K1_APAD * 2 * 4)

__global__ __launch_bounds__(256, 2) void qkv_mma_kernel(const float* __restrict__ x,
                                                         const float* __restrict__ Wq) {
    extern __shared__ uint32_t smu[];
    uint32_t* Ahi = smu;
    uint32_t* Alo = Ahi + 128 * K1_APAD;

    const int b = blockIdx.z, mt = blockIdx.y, n0 = blockIdx.x * 128;
    const int tid = threadIdx.x;

    for (int idx = tid; idx < 128 * 16; idx += 256) {
        int row = idx >> 4, c4 = (idx & 15) * 4;
        float4 w = *(const float4*)(Wq + (size_t)(mt * 128 + row) * CDIM + c4);
        float v[4] = {w.x, w.y, w.z, w.w};
#pragma unroll
        for (int j = 0; j < 4; j++) {
            uint32_t h = f2tf(v[j]);
            Ahi[row * K1_APAD + c4 + j] = h;
            Alo[row * K1_APAD + c4 + j] = f2tf(v[j] - __uint_as_float(h));
        }
    }
    __syncthreads();

    const int wid = tid >> 5, lane = tid & 31, g = lane >> 2, tig = lane & 3;
    const int wm = (wid >> 2) * 64, wn = (wid & 3) * 32;

    const float* xb = x + (size_t)b * CDIM * NPOS + n0;

    float c[4][4][4];
#pragma unroll
    for (int i = 0; i < 4; i++)
#pragma unroll
        for (int j = 0; j < 4; j++)
#pragma unroll
            for (int q = 0; q < 4; q++) c[i][j][q] = 0.f;

#pragma unroll
    for (int k8 = 0; k8 < 8; k8++) {
        const int kb = k8 * 8;
        const float* xr0 = xb + (size_t)(kb + tig) * NPOS;
        const float* xr1 = xr0 + 4 * NPOS;
        uint32_t bh[4][2], bl[4][2];
#pragma unroll
        for (int nf = 0; nf < 4; nf++) {
            int col = wn + nf * 8 + g;
            float v0 = __ldg(xr0 + col);
            float v1 = __ldg(xr1 + col);
            uint32_t h0 = f2tf(v0), h1 = f2tf(v1);
            bh[nf][0] = h0; bh[nf][1] = h1;
            bl[nf][0] = f2tf(v0 - __uint_as_float(h0));
            bl[nf][1] = f2tf(v1 - __uint_as_float(h1));
        }
        uint32_t ah[4][4], al[4][4];
#pragma unroll
        for (int mf = 0; mf < 4; mf++) {
            int r0 = (wm + mf * 16 + g) * K1_APAD + kb + tig;
            int r1 = r0 + 8 * K1_APAD;
            ah[mf][0] = Ahi[r0]; ah[mf][1] = Ahi[r1];
            ah[mf][2] = Ahi[r0 + 4]; ah[mf][3] = Ahi[r1 + 4];
            al[mf][0] = Alo[r0]; al[mf][1] = Alo[r1];
            al[mf][2] = Alo[r0 + 4]; al[mf][3] = Alo[r1 + 4];
        }
#pragma unroll
        for (int mf = 0; mf < 4; mf++)
#pragma unroll
            for (int nf = 0; nf < 4; nf++) {
                MMA(c[mf][nf], ah[mf], bh[nf]);
                MMA(c[mf][nf], ah[mf], bl[nf]);
                MMA(c[mf][nf], al[mf], bh[nf]);
            }
    }

    float* op = g_qkv + ((size_t)b * O3 + mt * 128 + wm) * NPOS + n0 + wn;
#pragma unroll
    for (int mf = 0; mf < 4; mf++)
#pragma unroll
        for (int nf = 0; nf < 4; nf++) {
            int col = nf * 8 + tig * 2;
            *(float2*)(op + (size_t)(mf * 16 + g) * NPOS + col) =
                make_float2(c[mf][nf][0], c[mf][nf][1]);
            *(float2*)(op + (size_t)(mf * 16 + g + 8) * NPOS + col) =
                make_float2(c[mf][nf][2], c[mf][nf][3]);
        }
}

// ---------------------------------------------------------------------------
// ATT2: partial (unnormalized) A over 128 positions. grid (9, 32, 8), 128 thr.
// (unchanged from R6)
// ---------------------------------------------------------------------------
#define A2_PAD 132
#define A2_ARR (DHEAD * A2_PAD)
#define A2_SMEM (4 * A2_ARR * 4)

__global__ __launch_bounds__(128, 3) void att_a_kernel() {
    extern __shared__ uint32_t sm2[];
    uint32_t* Eqh = sm2;
    uint32_t* Eql = Eqh + A2_ARR;
    uint32_t* Ksh = Eql + A2_ARR;
    uint32_t* Ksl = Ksh + A2_ARR;
    float* Apart = (float*)sm2;   // alias after mma: [4][32][33]

    const int ch = blockIdx.x, g = blockIdx.y, sub = blockIdx.z;
    const int gc = g * NCH + ch;
    const int b = g >> 2, head = g & 3;
    const int tid = threadIdx.x, lane = tid & 31, wrp = tid >> 5;
    const int j = tid;

    const float* qbase = g_qkv + ((size_t)(b * O3 + head * DHEAD)) * NPOS + ch * CHUNK + sub * 128;
    const float* kbase = qbase + (size_t)INNER * NPOS;

    float kr[DHEAD];
#pragma unroll
    for (int d = 0; d < DHEAD; d++) kr[d] = kbase[(size_t)d * NPOS + j];
    float km = -1e30f;
#pragma unroll
    for (int d = 0; d < DHEAD; d++) km = fmaxf(km, kr[d]);
    float ks = 0.f;
#pragma unroll
    for (int d = 0; d < DHEAD; d++) { kr[d] = __expf(kr[d] - km); ks += kr[d]; }
    float kinv = 1.0f / ks;
#pragma unroll
    for (int d = 0; d < DHEAD; d++) {
        float v = kr[d] * kinv;
        uint32_t h = f2tf(v);
        Ksh[d * A2_PAD + j] = h;
        Ksl[d * A2_PAD + j] = f2tf(v - __uint_as_float(h));
    }

    float qr[DHEAD];
#pragma unroll
    for (int d = 0; d < DHEAD; d++) qr[d] = qbase[(size_t)d * NPOS + j];
#pragma unroll
    for (int d = 0; d < DHEAD; d++) {
        float v = __expf(qr[d]);
        uint32_t h = f2tf(v);
        Eqh[d * A2_PAD + j] = h;
        Eql[d * A2_PAD + j] = f2tf(v - __uint_as_float(h));
    }
    __syncthreads();

    const int gq = lane >> 2, tig = lane & 3;
    float acc[2][4][4];
#pragma unroll
    for (int i = 0; i < 2; i++)
#pragma unroll
        for (int jj = 0; jj < 4; jj++)
#pragma unroll
            for (int q = 0; q < 4; q++) acc[i][jj][q] = 0.f;

#pragma unroll
    for (int kk = 0; kk < 4; kk++) {
        const int kb = (wrp * 4 + kk) * 8;
        uint32_t ah[2][4], al[2][4];
#pragma unroll
        for (int mf = 0; mf < 2; mf++) {
            int r0 = (mf * 16 + gq) * A2_PAD + kb + tig;
            int r1 = r0 + 8 * A2_PAD;
            ah[mf][0] = Eqh[r0]; ah[mf][1] = Eqh[r1];
            ah[mf][2] = Eqh[r0 + 4]; ah[mf][3] = Eqh[r1 + 4];
            al[mf][0] = Eql[r0]; al[mf][1] = Eql[r1];
            al[mf][2] = Eql[r0 + 4]; al[mf][3] = Eql[r1 + 4];
        }
        uint32_t bh[4][2], bl[4][2];
#pragma unroll
        for (int nf = 0; nf < 4; nf++) {
            int c0 = (nf * 8 + gq) * A2_PAD + kb + tig;
            bh[nf][0] = Ksh[c0]; bh[nf][1] = Ksh[c0 + 4];
            bl[nf][0] = Ksl[c0]; bl[nf][1] = Ksl[c0 + 4];
        }
#pragma unroll
        for (int mf = 0; mf < 2; mf++)
#pragma unroll
            for (int nf = 0; nf < 4; nf++) {
                MMA(acc[mf][nf], ah[mf], bh[nf]);
                MMA(acc[mf][nf], ah[mf], bl[nf]);
                MMA(acc[mf][nf], al[mf], bh[nf]);
            }
    }
    __syncthreads();

#pragma unroll
    for (int mf = 0; mf < 2; mf++)
#pragma unroll
        for (int nf = 0; nf < 4; nf++) {
            int row = mf * 16 + gq, col = nf * 8 + tig * 2;
            Apart[(wrp * 32 + row) * 33 + col]     = acc[mf][nf][0];
            Apart[(wrp * 32 + row) * 33 + col + 1] = acc[mf][nf][1];
            Apart[(wrp * 32 + row + 8) * 33 + col]     = acc[mf][nf][2];
            Apart[(wrp * 32 + row + 8) * 33 + col + 1] = acc[mf][nf][3];
        }
    __syncthreads();

    float* out = g_Apart[gc][sub];
#pragma unroll
    for (int r = 0; r < 8; r++) {
        int idx = tid + 128 * r;
        int d = idx >> 5, dp = idx & 31;
        float s = 0.f;
#pragma unroll
        for (int w = 0; w < 4; w++) s += Apart[(w * 32 + d) * 33 + dp];
        out[idx] = s;
    }
}

// ---------------------------------------------------------------------------
// WEFF1: per (ch, b, head): reduce A partials, 1/Zq from row sums, scale;
// Weff_head = Wout_blk @ A; W2_head = Weff_head @ Wv_head. grid (9,8,4).
// ---------------------------------------------------------------------------
__global__ __launch_bounds__(256, 4) void weff1_kernel(const float* __restrict__ Wqkv,
                                                       const float* __restrict__ Wout) {
    __shared__ float A_s[DHEAD][DHEAD + 1];
    __shared__ float Wo_s[CDIM][DHEAD + 1];
    __shared__ float Wv_s[DHEAD][CDIM + 1];
    __shared__ float Wef_s[CDIM][DHEAD + 1];
    __shared__ float rinv[DHEAD];
    const int ch = blockIdx.x, b = blockIdx.y, head = blockIdx.z;
    const int cc = b * NCH + ch;
    const int gc = (b * HEADS + head) * NCH + ch;
    const int tid = threadIdx.x;

    // reduce A partials over 8 sub-blocks
#pragma unroll
    for (int r = 0; r < 4; r++) {
        int idx = tid + 256 * r;
        const float* ap = g_Apart[gc][0] + idx;
        float s = 0.f;
#pragma unroll
        for (int sub = 0; sub < 8; sub++) s += ap[sub * DHEAD * DHEAD];
        A_s[idx >> 5][idx & 31] = s;
    }
    // stage W_out block [64][32] and Wv block [32][64]
#pragma unroll
    for (int r = 0; r < 8; r++) {
        int idx = tid + 256 * r;
        int o = idx >> 5, d = idx & 31;
        Wo_s[o][d] = Wout[(size_t)o * INNER + head * DHEAD + d];
    }
#pragma unroll
    for (int r = 0; r < 8; r++) {
        int idx = tid + 256 * r;
        int d = idx >> 6, c = idx & 63;
        Wv_s[d][c] = Wqkv[(size_t)(2 * INNER + head * DHEAD + d) * CDIM + c];
    }
    __syncthreads();

    // Zq[d] = sum_dp A[d][dp]
    if (tid < DHEAD) {
        float s = 0.f;
#pragma unroll
        for (int dp = 0; dp < DHEAD; dp++) s += A_s[tid][dp];
        rinv[tid] = 1.0f / s;
    }
    __syncthreads();
#pragma unroll
    for (int r = 0; r < 4; r++) {
        int idx = tid + 256 * r;
        A_s[idx >> 5][idx & 31] *= rinv[idx >> 5];
    }
    __syncthreads();

    // Weff_head[o][dp] = sum_d Wo_s[o][d] * A_s[d][dp]
#pragma unroll
    for (int r = 0; r < 8; r++) {
        int idx = tid + 256 * r;
        int o = idx >> 5, dp = idx & 31;
        float acc = 0.f;
#pragma unroll
        for (int d = 0; d < DHEAD; d++) acc += Wo_s[o][d] * A_s[d][dp];
        Wef_s[o][dp] = acc;
    }
    __syncthreads();

    // W2_head[o][c] = sum_dp Wef_s[o][dp] * Wv_s[dp][c]
    const int o = tid >> 2, c0 = (tid & 3) * 16;
    float w2[16];
#pragma unroll
    for (int i = 0; i < 16; i++) w2[i] = 0.f;
#pragma unroll
    for (int dp = 0; dp < DHEAD; dp++) {
        float wv = Wef_s[o][dp];
#pragma unroll
        for (int i = 0; i < 16; i++) w2[i] += wv * Wv_s[dp][c0 + i];
    }
    float* outp = g_W2part[cc][head] + o * CDIM + c0;
#pragma unroll
    for (int i = 0; i < 16; i++) outp[i] = w2[i];
}

// ---------------------------------------------------------------------------
// WEFF2: W2 = sum_heads W2_head, split to tf32 hi/lo. grid (9, 8), 256 thr.
// ---------------------------------------------------------------------------
__global__ __launch_bounds__(256, 8) void weff2_kernel() {
    const int ch = blockIdx.x, b = blockIdx.y;
    const int cc = b * NCH + ch;
    const int tid = threadIdx.x;
#pragma unroll
    for (int r = 0; r < 16; r++) {
        int idx = tid + 256 * r;
        float s = 0.f;
#pragma unroll
        for (int h = 0; h < HEADS; h++) s += g_W2part[cc][h][idx];
        uint32_t hh = f2tf(s);
        ((uint32_t*)&g_W2[cc][0][0][0])[idx] = hh;
        ((uint32_t*)&g_W2[cc][1][0][0])[idx] = f2tf(s - __uint_as_float(hh));
    }
}

// ---------------------------------------------------------------------------
// K3'' (fused): y = W2(b,ch) @ x + b_out, groupnorm partials.
// A (W2 hi/lo, padded) in smem; B (x) streamed from global (R6 form).
// CTA tile [64 M x 128 N], K=64. grid (72, 8), 256 threads, occ 2.
// ---------------------------------------------------------------------------
#define K3_PAD 68
#define K3_SMEM (64 * K3_PAD * 2 * 4)

__global__ __launch_bounds__(256, 2) void outproj_mma_kernel(const float* __restrict__ x,
                                                             const float* __restrict__ bout,
                                                             float* __restrict__ y) {
    extern __shared__ uint32_t smu[];
    uint32_t* Ahi = smu;
    uint32_t* Alo = Ahi + 64 * K3_PAD;
    __shared__ float swp[8][8][2];

    const int b = blockIdx.y, n0 = blockIdx.x * 128, tid = threadIdx.x;
    const int cc = b * NCH + (n0 / CHUNK);

    // stage pre-split W2 [64 M x 64 K]
    for (int idx = tid; idx < 64 * 16; idx += 256) {
        int row = idx >> 4, c4 = (idx & 15) * 4;
        float4 h4 = *(const float4*)(&g_W2[cc][0][row][c4]);
        float4 l4 = *(const float4*)(&g_W2[cc][1][row][c4]);
        Ahi[row * K3_PAD + c4]     = __float_as_uint(h4.x);
        Ahi[row * K3_PAD + c4 + 1] = __float_as_uint(h4.y);
        Ahi[row * K3_PAD + c4 + 2] = __float_as_uint(h4.z);
        Ahi[row * K3_PAD + c4 + 3] = __float_as_uint(h4.w);
        Alo[row * K3_PAD + c4]     = __float_as_uint(l4.x);
        Alo[row * K3_PAD + c4 + 1] = __float_as_uint(l4.y);
        Alo[row * K3_PAD + c4 + 2] = __float_as_uint(l4.z);
        Alo[row * K3_PAD + c4 + 3] = __float_as_uint(l4.w);
    }
    __syncthreads();

    const int wid = tid >> 5, lane = tid & 31, g = lane >> 2, tig = lane & 3;
    const int wn = wid * 16;
    const float* xb = x + (size_t)b * CDIM * NPOS + n0;

    float acc[4][2][4];
#pragma unroll
    for (int i = 0; i < 4; i++)
#pragma unroll
        for (int j = 0; j < 2; j++)
#pragma unroll
            for (int q = 0; q < 4; q++) acc[i][j][q] = 0.f;

#pragma unroll
    for (int k8 = 0; k8 < 8; k8++) {
        const int kb = k8 * 8;
        const float* xr0 = xb + (size_t)(kb + tig) * NPOS;
        const float* xr1 = xr0 + 4 * NPOS;
        uint32_t bh[2][2], bl[2][2];
#pragma unroll
        for (int nf = 0; nf < 2; nf++) {
            int col = wn + nf * 8 + g;
            float v0 = __ldg(xr0 + col);
            float v1 = __ldg(xr1 + col);
            uint32_t h0 = f2tf(v0), h1 = f2tf(v1);
            bh[nf][0] = h0; bh[nf][1] = h1;
            bl[nf][0] = f2tf(v0 - __uint_as_float(h0));
            bl[nf][1] = f2tf(v1 - __uint_as_float(h1));
        }
        uint32_t ah[4][4], al[4][4];
#pragma unroll
        for (int mf = 0; mf < 4; mf++) {
            int r0 = (mf * 16 + g) * K3_PAD + kb + tig;
            int r1 = r0 + 8 * K3_PAD;
            ah[mf][0] = Ahi[r0]; ah[mf][1] = Ahi[r1];
            ah[mf][2] = Ahi[r0 + 4]; ah[mf][3] = Ahi[r1 + 4];
            al[mf][0] = Alo[r0]; al[mf][1] = Alo[r1];
            al[mf][2] = Alo[r0 + 4]; al[mf][3] = Alo[r1 + 4];
        }
#pragma unroll
        for (int mf = 0; mf < 4; mf++)
#pragma unroll
            for (int nf = 0; nf < 2; nf++) {
                MMA(acc[mf][nf], ah[mf], bh[nf]);
                MMA(acc[mf][nf], ah[mf], bl[nf]);
                MMA(acc[mf][nf], al[mf], bh[nf]);
            }
    }

    float gs[8], gq[8];
#pragma unroll
    for (int i = 0; i < 8; i++) { gs[i] = 0.f; gq[i] = 0.f; }

    float* yp = y + (size_t)b * CDIM * NPOS + n0 + wn;
#pragma unroll
    for (int mf = 0; mf < 4; mf++) {
        float bias0 = __ldg(bout + mf * 16 + g);
        float bias1 = __ldg(bout + mf * 16 + g + 8);
#pragma unroll
        for (int nf = 0; nf < 2; nf++) {
            int col = nf * 8 + tig * 2;
            float v0 = acc[mf][nf][0] + bias0, v1 = acc[mf][nf][1] + bias0;
            float v2 = acc[mf][nf][2] + bias1, v3 = acc[mf][nf][3] + bias1;
            *(float2*)(yp + (size_t)(mf * 16 + g) * NPOS + col) = make_float2(v0, v1);
            *(float2*)(yp + (size_t)(mf * 16 + g + 8) * NPOS + col) = make_float2(v2, v3);
            gs[2 * mf]     += v0 + v1;
            gq[2 * mf]     += v0 * v0 + v1 * v1;
            gs[2 * mf + 1] += v2 + v3;
            gq[2 * mf + 1] += v2 * v2 + v3 * v3;
        }
    }

#pragma unroll
    for (int gr = 0; gr < 8; gr++) {
        float s = gs[gr], q = gq[gr];
        for (int off = 16; off; off >>= 1) {
            s += __shfl_xor_sync(0xffffffffu, s, off);
            q += __shfl_xor_sync(0xffffffffu, q, off);
        }
        if (lane == 0) { swp[wid][gr][0] = s; swp[wid][gr][1] = q; }
    }
    __syncthreads();
    if (tid < 16) {
        int gr = tid >> 1, qq = tid & 1;
        float s = 0.f;
#pragma unroll
        for (int w = 0; w < 8; w++) s += swp[w][gr][qq];
        g_part[b][gr][blockIdx.x][qq] = s;
    }
}

// ---------------------------------------------------------------------------
// K4: groupnorm finalize, float4-vectorized. grid (9, 8), 256 threads.
// ---------------------------------------------------------------------------
__global__ __launch_bounds__(256, 4) void gnorm_kernel(float* __restrict__ y,
                                                       const float* __restrict__ gamma,
                                                       const float* __restrict__ beta) {
    __shared__ float tmp[8][2];
    __shared__ float mu[8], rs[8];
    const int b = blockIdx.y, n0 = blockIdx.x * 1024, tid = threadIdx.x;

    if (tid < 16) {
        int g = tid >> 1, qq = tid & 1;
        float s = 0.f;
        for (int t = 0; t < GN_TILES; t++) s += g_part[b][g][t][qq];
        tmp[g][qq] = s;
    }
    __syncthreads();
    if (tid < 8) {
        const float invn = 1.0f / (8.0f * NPOS);
        float m = tmp[tid][0] * invn;
        float v = tmp[tid][1] * invn - m * m;
        mu[tid] = m;
        rs[tid] = rsqrtf(v + 1e-5f);
    }
    __syncthreads();

    float* yb = y + (size_t)b * CDIM * NPOS + n0 + tid * 4;
#pragma unroll 4
    for (int c = 0; c < CDIM; c++) {
        float4* p = (float4*)(yb + (size_t)c * NPOS);
        float4 v = *p;
        int g = c >> 3;
        float sc = rs[g] * __ldg(gamma + c);
        float sh = __ldg(beta + c) - mu[g] * sc;
        v.x = v.x * sc + sh;
        v.y = v.y * sc + sh;
        v.z = v.z * sc + sh;
        v.w = v.w * sc + sh;
        *p = v;
    }
}

// ---------------------------------------------------------------------------
extern "C" void kernel_launch(void* const* d_in, const int* in_sizes, int n_in,
                              void* d_out, int out_size) {
    const float* x     = (const float*)d_in[0];
    const float* Wqkv  = (const float*)d_in[1];
    const float* Wout  = (const float*)d_in[2];
    const float* bout  = (const float*)d_in[3];
    const float* gamma = (const float*)d_in[4];
    const float* beta  = (const float*)d_in[5];
    float* y = (float*)d_out;

    cudaFuncSetAttribute(qkv_mma_kernel, cudaFuncAttributeMaxDynamicSharedMemorySize, K1_SMEM);
    cudaFuncSetAttribute(att_a_kernel, cudaFuncAttributeMaxDynamicSharedMemorySize, A2_SMEM);
    cudaFuncSetAttribute(outproj_mma_kernel, cudaFuncAttributeMaxDynamicSharedMemorySize, K3_SMEM);

    qkv_mma_kernel<<<dim3(72, 2, B_), 256, K1_SMEM>>>(x, Wqkv);
    att_a_kernel<<<dim3(NCH, 32, 8), 128, A2_SMEM>>>();
    weff1_kernel<<<dim3(NCH, B_, HEADS), 256>>>(Wqkv, Wout);
    weff2_kernel<<<dim3(NCH, B_), 256>>>();
    outproj_mma_kernel<<<dim3(GN_TILES, B_), 256, K3_SMEM>>>(x, bout, y);
    gnorm_kernel<<<dim3(NCH, B_), 256>>>(y, gamma, beta);
}